// round 5
// baseline (speedup 1.0000x reference)
#include <cuda_runtime.h>
#include <cuda_fp16.h>

#define HID   128
#define MAXN  100000

// fp16 node tables (static __device__ — allocation guards forbid cudaMalloc)
__device__ __half g_Ah[MAXN * HID];   // 25.6 MB
__device__ __half g_Bh[MAXN * HID];   // 25.6 MB

// ---------- packed f32x2 helpers ----------
__device__ __forceinline__ unsigned long long pack2(float lo, float hi) {
    unsigned long long r;
    asm("mov.b64 %0, {%1, %2};" : "=l"(r) : "f"(lo), "f"(hi));
    return r;
}
__device__ __forceinline__ unsigned long long fma2(unsigned long long a,
                                                   unsigned long long b,
                                                   unsigned long long c) {
    unsigned long long d;
    asm("fma.rn.f32x2 %0, %1, %2, %3;" : "=l"(d) : "l"(a), "l"(b), "l"(c));
    return d;
}
__device__ __forceinline__ float2 unpack2(unsigned long long v) {
    float2 f;
    asm("mov.b64 {%0, %1}, %2;" : "=f"(f.x), "=f"(f.y) : "l"(v));
    return f;
}

// ---------------------------------------------------------------------------
// Precompute (persistent, 2 CTAs/SM, 16 warps):
//   half 0: g_Ah[n] = half( z_src[n] @ W1[0:128]   + b1 )
//   half 1: g_Bh[n] = half( z_dst[n] @ W1[128:256] )
// smem: W half [128][128] f32 (64 KB) + z-tile PRE-DUPLICATED {z,z} u64
// [128][32] (32 KB) = 96 KB. Mainloop per k per thread:
//   4x LDS.64 (W col-pairs, 16-lane broadcast) + 2x LDS.64 (z) + 8x FFMA2.
// Thread tile: 2 nodes (ng, ng+16) x 8 cols (cg*8..+7 as 4 f32x2 pairs).
// ---------------------------------------------------------------------------
__global__ __launch_bounds__(256, 2) void precompute_kernel(
    const float* __restrict__ zsrc, const float* __restrict__ zdst,
    const float* __restrict__ W1, const float* __restrict__ b1,
    int nNodes, int nTiles)
{
    extern __shared__ float smem[];
    float* sW = smem;                                                // 64 KB
    unsigned long long* sZd = (unsigned long long*)(smem + HID*HID); // 32 KB

    const int nb   = gridDim.x >> 1;
    const int half = (blockIdx.x >= nb) ? 1 : 0;
    const int bid  = half ? (blockIdx.x - nb) : blockIdx.x;

    const float* z   = half ? zdst : zsrc;
    __half*      out = half ? g_Bh : g_Ah;
    const float* Wh  = W1 + half * HID * HID;

    const int tid = threadIdx.x;

    // Load W half into shared (once per CTA)
    for (int i = tid; i < HID * HID / 4; i += 256)
        ((float4*)sW)[i] = ((const float4*)Wh)[i];

    const int ng = tid & 15;    // node group: nodes {ng, ng+16}
    const int cg = tid >> 4;    // col group (16 groups x 8 cols)

    unsigned long long binit[4];
    #pragma unroll
    for (int j = 0; j < 4; j++)
        binit[j] = half ? 0ULL : pack2(b1[cg*8 + 2*j], b1[cg*8 + 2*j + 1]);

    // Prefetch mapping: thread = (node nl 0..31, quarter q 0..7 of row)
    const int nl = tid >> 3;
    const int q  = tid & 7;

    float4 f[4];
    int t = bid;
    {
        int node = t * 32 + nl;
        if (t < nTiles && node < nNodes) {
            const float4* zr = (const float4*)(z + (size_t)node * HID) + q * 4;
            #pragma unroll
            for (int j = 0; j < 4; j++) f[j] = zr[j];
        } else {
            #pragma unroll
            for (int j = 0; j < 4; j++) f[j] = make_float4(0.f,0.f,0.f,0.f);
        }
    }

    for (; t < nTiles; t += nb) {
        __syncthreads();
        // Store current tile's z, duplicated {v,v}, layout sZd[k*32 + node]
        #pragma unroll
        for (int j = 0; j < 4; j++) {
            int kb = (q * 4 + j) * 4;
            sZd[(kb + 0) * 32 + nl] = pack2(f[j].x, f[j].x);
            sZd[(kb + 1) * 32 + nl] = pack2(f[j].y, f[j].y);
            sZd[(kb + 2) * 32 + nl] = pack2(f[j].z, f[j].z);
            sZd[(kb + 3) * 32 + nl] = pack2(f[j].w, f[j].w);
        }
        __syncthreads();

        // Prefetch next tile (overlaps mainloop)
        int tn = t + nb;
        if (tn < nTiles) {
            int node = tn * 32 + nl;
            if (node < nNodes) {
                const float4* zr = (const float4*)(z + (size_t)node * HID) + q * 4;
                #pragma unroll
                for (int j = 0; j < 4; j++) f[j] = zr[j];
            } else {
                #pragma unroll
                for (int j = 0; j < 4; j++) f[j] = make_float4(0.f,0.f,0.f,0.f);
            }
        }

        unsigned long long acc[2][4];
        #pragma unroll
        for (int i = 0; i < 2; i++)
            #pragma unroll
            for (int j = 0; j < 4; j++) acc[i][j] = binit[j];

        #pragma unroll 8
        for (int k = 0; k < HID; k++) {
            unsigned long long wp[4];
            #pragma unroll
            for (int j = 0; j < 4; j++)      // adjacent cols -> free pairs
                wp[j] = *(const unsigned long long*)&sW[k*HID + cg*8 + 2*j];
            unsigned long long zp0 = sZd[k*32 + ng];
            unsigned long long zp1 = sZd[k*32 + ng + 16];
            #pragma unroll
            for (int j = 0; j < 4; j++) {
                acc[0][j] = fma2(zp0, wp[j], acc[0][j]);
                acc[1][j] = fma2(zp1, wp[j], acc[1][j]);
            }
        }

        #pragma unroll
        for (int i = 0; i < 2; i++) {
            int node = t * 32 + ng + 16 * i;
            if (node >= nNodes) continue;
            __half2 h[4];
            #pragma unroll
            for (int j = 0; j < 4; j++) {
                float2 p = unpack2(acc[i][j]);
                h[j] = __floats2half2_rn(p.x, p.y);
            }
            *(uint4*)(out + (size_t)node * HID + cg * 8) = *(uint4*)h;
        }
    }
}

// ---------------------------------------------------------------------------
// Edge kernel (index convert fused): warp per 4 edges.
//   out[e] = relu(A[s]+B[d]) . W2 + b2   with fp16 A/B rows (256 B each).
// Lane l covers cols 4l..4l+3: uint2 (4-half) gathers, 8 in flight per group,
// 4 parallel shfl reduction chains, float4 output store from lane 0.
// ---------------------------------------------------------------------------
__global__ __launch_bounds__(256) void edge_kernel(
    const void* __restrict__ ps, const void* __restrict__ pd,
    const void* __restrict__ ns, const void* __restrict__ nd,
    const float* __restrict__ W2, const float* __restrict__ b2,
    float* __restrict__ out, int E2, int Eh, int nNodes)
{
    __shared__ int sF64;
    if (threadIdx.x == 0) {
        const long long* arrs[4] = {(const long long*)ps, (const long long*)pd,
                                    (const long long*)ns, (const long long*)nd};
        int step = (Eh / 2) / 8;
        if (step < 1) step = 1;
        int ok = 1;
        for (int a = 0; a < 4; a++)
            for (int j = 0; j < 8; j++) {
                long long v = arrs[a][(long long)j * step];
                if (v < 0 || v >= nNodes) ok = 0;
            }
        sF64 = ok;
    }
    __syncthreads();
    const int f64 = sF64;

    const int lane = threadIdx.x & 31;
    const int gw   = (blockIdx.x * blockDim.x + threadIdx.x) >> 5;
    const int nw   = (gridDim.x * blockDim.x) >> 5;

    const float4 w2v = ((const float4*)W2)[lane];
    const float  b2s = b2[0];
    const uint2* A2 = (const uint2*)g_Ah;   // row = 32 uint2
    const uint2* B2 = (const uint2*)g_Bh;

    auto ldidx = [&](const void* p, int i) -> int {
        long long v = f64 ? ((const long long*)p)[i]
                          : (long long)((const int*)p)[i];
        if (v < 0) v = 0;
        if (v >= nNodes) v = nNodes - 1;
        return (int)v;
    };
    auto edge_sd = [&](int e, int& s, int& d) {
        if (e < Eh) { s = ldidx(ps, e);       d = ldidx(pd, e); }
        else        { s = ldidx(ns, e - Eh);  d = ldidx(nd, e - Eh); }
    };
    auto dot4 = [&](uint2 a, uint2 b) -> float {
        float2 a0 = __half22float2(*(__half2*)&a.x);
        float2 a1 = __half22float2(*(__half2*)&a.y);
        float2 b0 = __half22float2(*(__half2*)&b.x);
        float2 b1 = __half22float2(*(__half2*)&b.y);
        return fmaxf(a0.x + b0.x, 0.f) * w2v.x
             + fmaxf(a0.y + b0.y, 0.f) * w2v.y
             + fmaxf(a1.x + b1.x, 0.f) * w2v.z
             + fmaxf(a1.y + b1.y, 0.f) * w2v.w;
    };

    const int E2r = E2 & ~3;

    for (int base = gw * 4; base < E2r; base += nw * 4) {
        int s0,d0,s1,d1,s2,d2,s3,d3;
        edge_sd(base + 0, s0, d0);
        edge_sd(base + 1, s1, d1);
        edge_sd(base + 2, s2, d2);
        edge_sd(base + 3, s3, d3);

        uint2 a0 = A2[(size_t)s0 * 32 + lane];
        uint2 b0 = B2[(size_t)d0 * 32 + lane];
        uint2 a1 = A2[(size_t)s1 * 32 + lane];
        uint2 b1 = B2[(size_t)d1 * 32 + lane];
        uint2 a2 = A2[(size_t)s2 * 32 + lane];
        uint2 b2u = B2[(size_t)d2 * 32 + lane];
        uint2 a3 = A2[(size_t)s3 * 32 + lane];
        uint2 b3 = B2[(size_t)d3 * 32 + lane];

        float p0 = dot4(a0, b0);
        float p1 = dot4(a1, b1);
        float p2 = dot4(a2, b2u);
        float p3 = dot4(a3, b3);

        #pragma unroll
        for (int off = 16; off; off >>= 1) {   // 4 independent chains
            p0 += __shfl_xor_sync(0xffffffffu, p0, off);
            p1 += __shfl_xor_sync(0xffffffffu, p1, off);
            p2 += __shfl_xor_sync(0xffffffffu, p2, off);
            p3 += __shfl_xor_sync(0xffffffffu, p3, off);
        }

        if (lane == 0)
            *(float4*)&out[base] = make_float4(p0+b2s, p1+b2s, p2+b2s, p3+b2s);
    }

    // Tail (E2 not divisible by 4): first warp, scalar.
    if (gw == 0) {
        for (int e = E2r; e < E2; e++) {
            int s, d;
            edge_sd(e, s, d);
            uint2 a = A2[(size_t)s * 32 + lane];
            uint2 b = B2[(size_t)d * 32 + lane];
            float p = dot4(a, b);
            #pragma unroll
            for (int off = 16; off; off >>= 1)
                p += __shfl_xor_sync(0xffffffffu, p, off);
            if (lane == 0) out[e] = p + b2s;
        }
    }
}

// ---------------------------------------------------------------------------
extern "C" void kernel_launch(void* const* d_in, const int* in_sizes, int n_in,
                              void* d_out, int out_size)
{
    // Resolve input ordering: dict order vs name-sorted order.
    const float *zsrc, *zdst, *W1, *b1, *W2, *b2;
    const void  *ps, *pd, *ns, *nd;
    int zElems, eElems;
    if (in_sizes[0] == 2 * HID * HID) {
        // name-sorted: W1, W2, b1, b2, neg_dst, neg_src, pos_dst, pos_src, z_dst, z_src
        W1 = (const float*)d_in[0];
        W2 = (const float*)d_in[1];
        b1 = (const float*)d_in[2];
        b2 = (const float*)d_in[3];
        nd = d_in[4]; ns = d_in[5];
        pd = d_in[6]; ps = d_in[7];
        zdst = (const float*)d_in[8];
        zsrc = (const float*)d_in[9];
        zElems = in_sizes[8];
        eElems = in_sizes[4];
    } else {
        // dict order: z_src, z_dst, pos_src, pos_dst, neg_src, neg_dst, W1, b1, W2, b2
        zsrc = (const float*)d_in[0];
        zdst = (const float*)d_in[1];
        ps = d_in[2]; pd = d_in[3];
        ns = d_in[4]; nd = d_in[5];
        W1 = (const float*)d_in[6];
        b1 = (const float*)d_in[7];
        W2 = (const float*)d_in[8];
        b2 = (const float*)d_in[9];
        zElems = in_sizes[0];
        eElems = in_sizes[2];
    }

    int nNodes = zElems / HID;
    if (nNodes > MAXN) nNodes = MAXN;
    const int E2 = out_size;   // 2E
    const int Eh = eElems;     // E
    const int nTiles = (nNodes + 31) / 32;

    const int smem = (HID * HID) * 4 + (HID * 32) * 8;   // 98304 B
    cudaFuncSetAttribute(precompute_kernel,
                         cudaFuncAttributeMaxDynamicSharedMemorySize, smem);

    int nb = 296;                       // persistent CTAs per half (2/SM)
    if (nb > nTiles) nb = nTiles;
    precompute_kernel<<<2 * nb, 256, smem>>>(zsrc, zdst, W1, b1, nNodes, nTiles);

    edge_kernel<<<8192, 256>>>(ps, pd, ns, nd, W2, b2,
                               (float*)d_out, E2, Eh, nNodes);
}

// round 8
// speedup vs baseline: 2.3372x; 2.3372x over previous
#include <cuda_runtime.h>
#include <cuda_fp16.h>
#include <cstdint>

#define HID   128
#define MAXN  100000

// Static device scratch (allocation guards forbid cudaMalloc)
__device__ __half g_Ah[MAXN * HID];   // 25.6 MB  fp16 table A
__device__ __half g_Bh[MAXN * HID];   // 25.6 MB  fp16 table B
__device__ __half g_Wt[2 * HID * HID];// W1^T fp16: [half][n][k]

// ---------------------------------------------------------------------------
// W prep: g_Wt[half][n][k] = W1[half*128 + k][n]   (B operand, col-major k x n)
// ---------------------------------------------------------------------------
__global__ void wprep_kernel(const float* __restrict__ W1)
{
    int i = blockIdx.x * blockDim.x + threadIdx.x;
    if (i >= 2 * HID * HID) return;
    int half = i >> 14, r = i & 16383, n = r >> 7, k = r & 127;
    g_Wt[i] = __float2half(W1[(half * HID + k) * HID + n]);
}

// ---------------------------------------------------------------------------
// GEMM precompute via mma.sync (HMMA, PTX-portable):
//   half 0: g_Ah[tile] = half( z_src_tile[128x128] @ W1top + b1 )
//   half 1: g_Bh[tile] = half( z_dst_tile[128x128] @ W1bot )
// CTA: 256 thr (8 warps), tile M=128,N=128,K=128.
// Warp tile 32x64: 2 Mtiles x 8 Ntiles of m16n8k16, 8 k-steps.
// smem: sA z-half [128][136], sB Wt [128][136]  (padded, conflict-free).
// ---------------------------------------------------------------------------
#define SSTR 136   // smem row stride in halfs (272 B = 17*16, uint4-aligned)

__global__ __launch_bounds__(256) void gemm_kernel(
    const float* __restrict__ zsrc, const float* __restrict__ zdst,
    const float* __restrict__ b1, int nNodes, int nT)
{
    extern __shared__ __half smem[];
    __half* sA = smem;              // [128][SSTR]
    __half* sB = smem + 128 * SSTR; // [128][SSTR]

    const int half = (blockIdx.x >= (unsigned)nT) ? 1 : 0;
    const int t    = blockIdx.x - half * nT;
    const float* z = half ? zdst : zsrc;
    __half*    tab = half ? g_Bh : g_Ah;

    const int tid  = threadIdx.x;
    const int wid  = tid >> 5;
    const int lane = tid & 31;
    const int grp  = lane >> 2;     // 0..7
    const int tig  = lane & 3;      // 0..3

    // ---- load W^T into sB: [n][k], stride SSTR ----
    {
        const uint4* wb = (const uint4*)(g_Wt + half * HID * HID);
        #pragma unroll 4
        for (int i = tid; i < 2048; i += 256) {       // 2048 uint4 = 16384 halfs
            int n = i >> 4, k0 = (i & 15) * 8;
            *(uint4*)(sB + n * SSTR + k0) = wb[i];
        }
    }
    // ---- load z tile fp32 -> half into sA: [m][k], stride SSTR ----
    {
        const float4* zg = (const float4*)z;
        const size_t base4 = (size_t)t * 4096;        // 128 rows * 32 float4
        const size_t lim4  = (size_t)nNodes * 32;
        #pragma unroll 4
        for (int i = tid; i < 4096; i += 256) {
            float4 v = make_float4(0.f, 0.f, 0.f, 0.f);
            size_t g = base4 + i;
            if (g < lim4) v = zg[g];
            int row = i >> 5, c0 = (i & 31) * 4;
            __half2 h0 = __floats2half2_rn(v.x, v.y);
            __half2 h1 = __floats2half2_rn(v.z, v.w);
            *(uint32_t*)(sA + row * SSTR + c0)     = *(uint32_t*)&h0;
            *(uint32_t*)(sA + row * SSTR + c0 + 2) = *(uint32_t*)&h1;
        }
    }
    __syncthreads();

    const int m_base = (wid >> 1) * 32;   // 4 M-quadrants
    const int n_base = (wid & 1) * 64;    // 2 N-halves

    float c[2][8][4];
    #pragma unroll
    for (int mt = 0; mt < 2; mt++)
        #pragma unroll
        for (int nt = 0; nt < 8; nt++)
            #pragma unroll
            for (int j = 0; j < 4; j++) c[mt][nt][j] = 0.f;

    #pragma unroll
    for (int ks = 0; ks < 8; ks++) {
        const int k0 = ks * 16;
        uint32_t a[2][4], b[8][2];
        #pragma unroll
        for (int mt = 0; mt < 2; mt++) {
            const __half* pr = sA + (m_base + mt * 16 + grp) * SSTR + k0 + tig * 2;
            a[mt][0] = *(const uint32_t*)pr;
            a[mt][1] = *(const uint32_t*)(pr + 8 * SSTR);
            a[mt][2] = *(const uint32_t*)(pr + 8);
            a[mt][3] = *(const uint32_t*)(pr + 8 * SSTR + 8);
        }
        #pragma unroll
        for (int nt = 0; nt < 8; nt++) {
            const __half* pb = sB + (n_base + nt * 8 + grp) * SSTR + k0 + tig * 2;
            b[nt][0] = *(const uint32_t*)pb;
            b[nt][1] = *(const uint32_t*)(pb + 8);
        }
        #pragma unroll
        for (int mt = 0; mt < 2; mt++)
            #pragma unroll
            for (int nt = 0; nt < 8; nt++)
                asm volatile(
                    "mma.sync.aligned.m16n8k16.row.col.f32.f16.f16.f32 "
                    "{%0,%1,%2,%3}, {%4,%5,%6,%7}, {%8,%9}, {%0,%1,%2,%3};"
                    : "+f"(c[mt][nt][0]), "+f"(c[mt][nt][1]),
                      "+f"(c[mt][nt][2]), "+f"(c[mt][nt][3])
                    : "r"(a[mt][0]), "r"(a[mt][1]), "r"(a[mt][2]), "r"(a[mt][3]),
                      "r"(b[nt][0]), "r"(b[nt][1]));
    }
    __syncthreads();    // done reading sA/sB; reuse sA as output stage

    // ---- epilogue: bias (half 0), fp16 pack, stage to sA [m][SSTR] ----
    #pragma unroll
    for (int nt = 0; nt < 8; nt++) {
        const int col = n_base + nt * 8 + tig * 2;
        float bx = 0.f, by = 0.f;
        if (half == 0) { bx = b1[col]; by = b1[col + 1]; }
        #pragma unroll
        for (int mt = 0; mt < 2; mt++) {
            const int r0 = m_base + mt * 16 + grp;
            __half2 h0 = __floats2half2_rn(c[mt][nt][0] + bx, c[mt][nt][1] + by);
            __half2 h1 = __floats2half2_rn(c[mt][nt][2] + bx, c[mt][nt][3] + by);
            *(uint32_t*)(sA + r0 * SSTR + col)       = *(uint32_t*)&h0;
            *(uint32_t*)(sA + (r0 + 8) * SSTR + col) = *(uint32_t*)&h1;
        }
    }
    __syncthreads();

    // ---- coalesced store: 2048 uint4 (128 rows x 16 uint4) ----
    {
        #pragma unroll 4
        for (int i = tid; i < 2048; i += 256) {       // FIXED: was 4096
            int row = i >> 4, c8 = (i & 15) * 8;
            int node = t * 128 + row;
            if (node < nNodes)
                *(uint4*)(tab + (size_t)node * HID + c8) =
                    *(const uint4*)(sA + row * SSTR + c8);
        }
    }
}

// ---------------------------------------------------------------------------
// Edge kernel (index convert fused): warp per 4 edges, fp16 tables.
//   out[e] = relu(A[s]+B[d]) . W2 + b2 ; relu+add in half2, 4 cvt per edge.
// ---------------------------------------------------------------------------
__global__ __launch_bounds__(256) void edge_kernel(
    const void* __restrict__ ps, const void* __restrict__ pd,
    const void* __restrict__ ns, const void* __restrict__ nd,
    const float* __restrict__ W2, const float* __restrict__ b2,
    float* __restrict__ out, int E2, int Eh, int nNodes)
{
    __shared__ int sF64;
    if (threadIdx.x == 0) {
        const long long* arrs[4] = {(const long long*)ps, (const long long*)pd,
                                    (const long long*)ns, (const long long*)nd};
        int step = (Eh / 2) / 8;
        if (step < 1) step = 1;
        int ok = 1;
        for (int a = 0; a < 4; a++)
            for (int j = 0; j < 8; j++) {
                long long v = arrs[a][(long long)j * step];
                if (v < 0 || v >= nNodes) ok = 0;
            }
        sF64 = ok;
    }
    __syncthreads();
    const int f64 = sF64;

    const int lane = threadIdx.x & 31;
    const int gw   = (blockIdx.x * blockDim.x + threadIdx.x) >> 5;
    const int nw   = (gridDim.x * blockDim.x) >> 5;

    const float4 w2v = ((const float4*)W2)[lane];
    const float  b2s = b2[0];
    const uint2* A2 = (const uint2*)g_Ah;   // row = 32 uint2 (256 B)
    const uint2* B2 = (const uint2*)g_Bh;
    const __half2 hz = __float2half2_rn(0.f);

    auto ldidx = [&](const void* p, int i) -> int {
        long long v = f64 ? ((const long long*)p)[i]
                          : (long long)((const int*)p)[i];
        if (v < 0) v = 0;
        if (v >= nNodes) v = nNodes - 1;
        return (int)v;
    };
    auto edge_sd = [&](int e, int& s, int& d) {
        if (e < Eh) { s = ldidx(ps, e);       d = ldidx(pd, e); }
        else        { s = ldidx(ns, e - Eh);  d = ldidx(nd, e - Eh); }
    };
    auto dot4 = [&](uint2 a, uint2 b) -> float {
        __half2 s0 = __hmax2(__hadd2(*(__half2*)&a.x, *(__half2*)&b.x), hz);
        __half2 s1 = __hmax2(__hadd2(*(__half2*)&a.y, *(__half2*)&b.y), hz);
        float2 f0 = __half22float2(s0);
        float2 f1 = __half22float2(s1);
        return f0.x * w2v.x + f0.y * w2v.y + f1.x * w2v.z + f1.y * w2v.w;
    };

    const int E2r = E2 & ~3;

    for (int base = gw * 4; base < E2r; base += nw * 4) {
        int s0,d0,s1,d1,s2,d2,s3,d3;
        edge_sd(base + 0, s0, d0);
        edge_sd(base + 1, s1, d1);
        edge_sd(base + 2, s2, d2);
        edge_sd(base + 3, s3, d3);

        uint2 a0 = A2[(size_t)s0 * 32 + lane];
        uint2 b0 = B2[(size_t)d0 * 32 + lane];
        uint2 a1 = A2[(size_t)s1 * 32 + lane];
        uint2 b1v = B2[(size_t)d1 * 32 + lane];
        uint2 a2 = A2[(size_t)s2 * 32 + lane];
        uint2 b2u = B2[(size_t)d2 * 32 + lane];
        uint2 a3 = A2[(size_t)s3 * 32 + lane];
        uint2 b3 = B2[(size_t)d3 * 32 + lane];

        float p0 = dot4(a0, b0);
        float p1 = dot4(a1, b1v);
        float p2 = dot4(a2, b2u);
        float p3 = dot4(a3, b3);

        #pragma unroll
        for (int off = 16; off; off >>= 1) {   // 4 independent chains
            p0 += __shfl_xor_sync(0xffffffffu, p0, off);
            p1 += __shfl_xor_sync(0xffffffffu, p1, off);
            p2 += __shfl_xor_sync(0xffffffffu, p2, off);
            p3 += __shfl_xor_sync(0xffffffffu, p3, off);
        }

        if (lane == 0)
            *(float4*)&out[base] = make_float4(p0+b2s, p1+b2s, p2+b2s, p3+b2s);
    }

    if (gw == 0) {                       // tail
        for (int e = E2r; e < E2; e++) {
            int s, d;
            edge_sd(e, s, d);
            uint2 a = A2[(size_t)s * 32 + lane];
            uint2 b = B2[(size_t)d * 32 + lane];
            float p = dot4(a, b);
            #pragma unroll
            for (int off = 16; off; off >>= 1)
                p += __shfl_xor_sync(0xffffffffu, p, off);
            if (lane == 0) out[e] = p + b2s;
        }
    }
}

// ---------------------------------------------------------------------------
extern "C" void kernel_launch(void* const* d_in, const int* in_sizes, int n_in,
                              void* d_out, int out_size)
{
    const float *zsrc, *zdst, *W1, *b1, *W2, *b2;
    const void  *ps, *pd, *ns, *nd;
    int zElems, eElems;
    if (in_sizes[0] == 2 * HID * HID) {
        // name-sorted: W1, W2, b1, b2, neg_dst, neg_src, pos_dst, pos_src, z_dst, z_src
        W1 = (const float*)d_in[0];
        W2 = (const float*)d_in[1];
        b1 = (const float*)d_in[2];
        b2 = (const float*)d_in[3];
        nd = d_in[4]; ns = d_in[5];
        pd = d_in[6]; ps = d_in[7];
        zdst = (const float*)d_in[8];
        zsrc = (const float*)d_in[9];
        zElems = in_sizes[8];
        eElems = in_sizes[4];
    } else {
        // dict order: z_src, z_dst, pos_src, pos_dst, neg_src, neg_dst, W1, b1, W2, b2
        zsrc = (const float*)d_in[0];
        zdst = (const float*)d_in[1];
        ps = d_in[2]; pd = d_in[3];
        ns = d_in[4]; nd = d_in[5];
        W1 = (const float*)d_in[6];
        b1 = (const float*)d_in[7];
        W2 = (const float*)d_in[8];
        b2 = (const float*)d_in[9];
        zElems = in_sizes[0];
        eElems = in_sizes[2];
    }

    int nNodes = zElems / HID;
    if (nNodes > MAXN) nNodes = MAXN;
    const int E2 = out_size;   // 2E
    const int Eh = eElems;     // E
    const int nT = (nNodes + 127) / 128;

    const int smem = 2 * 128 * SSTR * (int)sizeof(__half);   // 69632 B
    cudaFuncSetAttribute(gemm_kernel,
                         cudaFuncAttributeMaxDynamicSharedMemorySize, smem);

    wprep_kernel<<<128, 256>>>(W1);
    gemm_kernel<<<2 * nT, 256, smem>>>(zsrc, zdst, b1, nNodes, nT);
    edge_kernel<<<8192, 256>>>(ps, pd, ns, nd, W2, b2,
                               (float*)d_out, E2, Eh, nNodes);
}

// round 9
// speedup vs baseline: 2.6019x; 1.1132x over previous
#include <cuda_runtime.h>
#include <cuda_fp16.h>
#include <cstdint>

#define HID   128
#define MAXN  100000

// Static device scratch (allocation guards forbid cudaMalloc)
__device__ __half g_Ah[MAXN * HID];   // 25.6 MB  fp16 table A
__device__ __half g_Bh[MAXN * HID];   // 25.6 MB  fp16 table B
__device__ __half g_Wt[2 * HID * HID];// W1^T fp16: [half][n][k]

// ---------------------------------------------------------------------------
// W prep: g_Wt[half][n][k] = W1[half*128 + k][n]   (B operand, col-major k x n)
// ---------------------------------------------------------------------------
__global__ void wprep_kernel(const float* __restrict__ W1)
{
    int i = blockIdx.x * blockDim.x + threadIdx.x;
    if (i >= 2 * HID * HID) return;
    int half = i >> 14, r = i & 16383, n = r >> 7, k = r & 127;
    g_Wt[i] = __float2half(W1[(half * HID + k) * HID + n]);
}

// ---------------------------------------------------------------------------
// GEMM precompute via mma.sync (HMMA, PTX-portable):
//   half 0: g_Ah[tile] = half( z_src_tile[128x128] @ W1top + b1 )
//   half 1: g_Bh[tile] = half( z_dst_tile[128x128] @ W1bot )
// CTA: 256 thr (8 warps), tile M=128,N=128,K=128.
// Warp tile 32x64: 2 Mtiles x 8 Ntiles of m16n8k16, 8 k-steps.
// smem: sA z-half [128][136], sB Wt [128][136]  (padded, conflict-free).
// ---------------------------------------------------------------------------
#define SSTR 136   // smem row stride in halfs (272 B = 17*16, uint4-aligned)

__global__ __launch_bounds__(256) void gemm_kernel(
    const float* __restrict__ zsrc, const float* __restrict__ zdst,
    const float* __restrict__ b1, int nNodes, int nT)
{
    extern __shared__ __half smem[];
    __half* sA = smem;              // [128][SSTR]
    __half* sB = smem + 128 * SSTR; // [128][SSTR]

    const int half = (blockIdx.x >= (unsigned)nT) ? 1 : 0;
    const int t    = blockIdx.x - half * nT;
    const float* z = half ? zdst : zsrc;
    __half*    tab = half ? g_Bh : g_Ah;

    const int tid  = threadIdx.x;
    const int wid  = tid >> 5;
    const int lane = tid & 31;
    const int grp  = lane >> 2;     // 0..7
    const int tig  = lane & 3;      // 0..3

    // ---- load W^T into sB: [n][k], stride SSTR ----
    {
        const uint4* wb = (const uint4*)(g_Wt + half * HID * HID);
        #pragma unroll 4
        for (int i = tid; i < 2048; i += 256) {       // 2048 uint4 = 16384 halfs
            int n = i >> 4, k0 = (i & 15) * 8;
            *(uint4*)(sB + n * SSTR + k0) = wb[i];
        }
    }
    // ---- load z tile fp32 -> half into sA: [m][k], stride SSTR ----
    {
        const float4* zg = (const float4*)z;
        const size_t base4 = (size_t)t * 4096;        // 128 rows * 32 float4
        const size_t lim4  = (size_t)nNodes * 32;
        #pragma unroll 4
        for (int i = tid; i < 4096; i += 256) {
            float4 v = make_float4(0.f, 0.f, 0.f, 0.f);
            size_t g = base4 + i;
            if (g < lim4) v = zg[g];
            int row = i >> 5, c0 = (i & 31) * 4;
            __half2 h0 = __floats2half2_rn(v.x, v.y);
            __half2 h1 = __floats2half2_rn(v.z, v.w);
            *(uint32_t*)(sA + row * SSTR + c0)     = *(uint32_t*)&h0;
            *(uint32_t*)(sA + row * SSTR + c0 + 2) = *(uint32_t*)&h1;
        }
    }
    __syncthreads();

    const int m_base = (wid >> 1) * 32;   // 4 M-quadrants
    const int n_base = (wid & 1) * 64;    // 2 N-halves

    float c[2][8][4];
    #pragma unroll
    for (int mt = 0; mt < 2; mt++)
        #pragma unroll
        for (int nt = 0; nt < 8; nt++)
            #pragma unroll
            for (int j = 0; j < 4; j++) c[mt][nt][j] = 0.f;

    #pragma unroll
    for (int ks = 0; ks < 8; ks++) {
        const int k0 = ks * 16;
        uint32_t a[2][4], b[8][2];
        #pragma unroll
        for (int mt = 0; mt < 2; mt++) {
            const __half* pr = sA + (m_base + mt * 16 + grp) * SSTR + k0 + tig * 2;
            a[mt][0] = *(const uint32_t*)pr;
            a[mt][1] = *(const uint32_t*)(pr + 8 * SSTR);
            a[mt][2] = *(const uint32_t*)(pr + 8);
            a[mt][3] = *(const uint32_t*)(pr + 8 * SSTR + 8);
        }
        #pragma unroll
        for (int nt = 0; nt < 8; nt++) {
            const __half* pb = sB + (n_base + nt * 8 + grp) * SSTR + k0 + tig * 2;
            b[nt][0] = *(const uint32_t*)pb;
            b[nt][1] = *(const uint32_t*)(pb + 8);
        }
        #pragma unroll
        for (int mt = 0; mt < 2; mt++)
            #pragma unroll
            for (int nt = 0; nt < 8; nt++)
                asm volatile(
                    "mma.sync.aligned.m16n8k16.row.col.f32.f16.f16.f32 "
                    "{%0,%1,%2,%3}, {%4,%5,%6,%7}, {%8,%9}, {%0,%1,%2,%3};"
                    : "+f"(c[mt][nt][0]), "+f"(c[mt][nt][1]),
                      "+f"(c[mt][nt][2]), "+f"(c[mt][nt][3])
                    : "r"(a[mt][0]), "r"(a[mt][1]), "r"(a[mt][2]), "r"(a[mt][3]),
                      "r"(b[nt][0]), "r"(b[nt][1]));
    }
    __syncthreads();    // done reading sA/sB; reuse sA as output stage

    // ---- epilogue: bias (half 0), fp16 pack, stage to sA [m][SSTR] ----
    #pragma unroll
    for (int nt = 0; nt < 8; nt++) {
        const int col = n_base + nt * 8 + tig * 2;
        float bx = 0.f, by = 0.f;
        if (half == 0) { bx = b1[col]; by = b1[col + 1]; }
        #pragma unroll
        for (int mt = 0; mt < 2; mt++) {
            const int r0 = m_base + mt * 16 + grp;
            __half2 h0 = __floats2half2_rn(c[mt][nt][0] + bx, c[mt][nt][1] + by);
            __half2 h1 = __floats2half2_rn(c[mt][nt][2] + bx, c[mt][nt][3] + by);
            *(uint32_t*)(sA + r0 * SSTR + col)       = *(uint32_t*)&h0;
            *(uint32_t*)(sA + (r0 + 8) * SSTR + col) = *(uint32_t*)&h1;
        }
    }
    __syncthreads();

    // ---- coalesced store: 2048 uint4 (128 rows x 16 uint4) ----
    {
        #pragma unroll 4
        for (int i = tid; i < 2048; i += 256) {
            int row = i >> 4, c8 = (i & 15) * 8;
            int node = t * 128 + row;
            if (node < nNodes)
                *(uint4*)(tab + (size_t)node * HID + c8) =
                    *(const uint4*)(sA + row * SSTR + c8);
        }
    }
}

// ---------------------------------------------------------------------------
// Edge kernel: warp = 4 edges, 8 LANES PER EDGE (lane: eg=lane>>3, cg=lane&7).
// Each lane: 1 index pair, 2x uint4 from A + 2x uint4 from B (16 cols), dot,
// then ONE 3-level shfl_xor(1,2,4) reduction serves all 4 edges (3 SHFL vs 20).
// ---------------------------------------------------------------------------
__global__ __launch_bounds__(256) void edge_kernel(
    const void* __restrict__ ps, const void* __restrict__ pd,
    const void* __restrict__ ns, const void* __restrict__ nd,
    const float* __restrict__ W2, const float* __restrict__ b2,
    float* __restrict__ out, int E2, int Eh, int nNodes)
{
    __shared__ int sF64;
    if (threadIdx.x == 0) {
        const long long* arrs[4] = {(const long long*)ps, (const long long*)pd,
                                    (const long long*)ns, (const long long*)nd};
        int step = (Eh / 2) / 8;
        if (step < 1) step = 1;
        int ok = 1;
        for (int a = 0; a < 4; a++)
            for (int j = 0; j < 8; j++) {
                long long v = arrs[a][(long long)j * step];
                if (v < 0 || v >= nNodes) ok = 0;
            }
        sF64 = ok;
    }
    __syncthreads();
    const int f64 = sF64;

    const int lane = threadIdx.x & 31;
    const int eg   = lane >> 3;     // which of 4 edges
    const int cg   = lane & 7;      // 16-col group within the edge
    const int gw   = (blockIdx.x * blockDim.x + threadIdx.x) >> 5;
    const int nw   = (gridDim.x * blockDim.x) >> 5;

    // W2 slice for this lane's 16 columns
    const float4 w0 = ((const float4*)W2)[cg * 4 + 0];
    const float4 w1 = ((const float4*)W2)[cg * 4 + 1];
    const float4 w2_ = ((const float4*)W2)[cg * 4 + 2];
    const float4 w3 = ((const float4*)W2)[cg * 4 + 3];
    const float  b2s = b2[0];
    const uint4* A4 = (const uint4*)g_Ah;   // row = 16 uint4 (256 B)
    const uint4* B4 = (const uint4*)g_Bh;
    const __half2 hz = __float2half2_rn(0.f);

    auto ldidx = [&](const void* p, int i) -> int {
        long long v = f64 ? ((const long long*)p)[i]
                          : (long long)((const int*)p)[i];
        if (v < 0) v = 0;
        if (v >= nNodes) v = nNodes - 1;
        return (int)v;
    };
    auto dot8 = [&](uint4 a, uint4 b, float4 wA, float4 wB) -> float {
        __half2 s0 = __hmax2(__hadd2(*(__half2*)&a.x, *(__half2*)&b.x), hz);
        __half2 s1 = __hmax2(__hadd2(*(__half2*)&a.y, *(__half2*)&b.y), hz);
        __half2 s2 = __hmax2(__hadd2(*(__half2*)&a.z, *(__half2*)&b.z), hz);
        __half2 s3 = __hmax2(__hadd2(*(__half2*)&a.w, *(__half2*)&b.w), hz);
        float2 f0 = __half22float2(s0);
        float2 f1 = __half22float2(s1);
        float2 f2 = __half22float2(s2);
        float2 f3 = __half22float2(s3);
        return f0.x*wA.x + f0.y*wA.y + f1.x*wA.z + f1.y*wA.w
             + f2.x*wB.x + f2.y*wB.y + f3.x*wB.z + f3.y*wB.w;
    };

    for (int base = gw * 4; base < E2; base += nw * 4) {
        int e = base + eg;
        int s = 0, d = 0;
        if (e < E2) {
            if (e < Eh) { s = ldidx(ps, e);      d = ldidx(pd, e); }
            else        { s = ldidx(ns, e - Eh); d = ldidx(nd, e - Eh); }
        }

        const size_t sr = (size_t)s * 16 + cg * 2;
        const size_t dr = (size_t)d * 16 + cg * 2;
        uint4 a0 = A4[sr],     b0 = B4[dr];
        uint4 a1 = A4[sr + 1], b1 = B4[dr + 1];

        float p = dot8(a0, b0, w0, w1) + dot8(a1, b1, w2_, w3);

        // 8-lane group reduction: one shfl serves all 4 edges
        p += __shfl_xor_sync(0xffffffffu, p, 1);
        p += __shfl_xor_sync(0xffffffffu, p, 2);
        p += __shfl_xor_sync(0xffffffffu, p, 4);

        if (cg == 0 && e < E2) out[e] = p + b2s;
    }
}

// ---------------------------------------------------------------------------
extern "C" void kernel_launch(void* const* d_in, const int* in_sizes, int n_in,
                              void* d_out, int out_size)
{
    const float *zsrc, *zdst, *W1, *b1, *W2, *b2;
    const void  *ps, *pd, *ns, *nd;
    int zElems, eElems;
    if (in_sizes[0] == 2 * HID * HID) {
        // name-sorted: W1, W2, b1, b2, neg_dst, neg_src, pos_dst, pos_src, z_dst, z_src
        W1 = (const float*)d_in[0];
        W2 = (const float*)d_in[1];
        b1 = (const float*)d_in[2];
        b2 = (const float*)d_in[3];
        nd = d_in[4]; ns = d_in[5];
        pd = d_in[6]; ps = d_in[7];
        zdst = (const float*)d_in[8];
        zsrc = (const float*)d_in[9];
        zElems = in_sizes[8];
        eElems = in_sizes[4];
    } else {
        // dict order: z_src, z_dst, pos_src, pos_dst, neg_src, neg_dst, W1, b1, W2, b2
        zsrc = (const float*)d_in[0];
        zdst = (const float*)d_in[1];
        ps = d_in[2]; pd = d_in[3];
        ns = d_in[4]; nd = d_in[5];
        W1 = (const float*)d_in[6];
        b1 = (const float*)d_in[7];
        W2 = (const float*)d_in[8];
        b2 = (const float*)d_in[9];
        zElems = in_sizes[0];
        eElems = in_sizes[2];
    }

    int nNodes = zElems / HID;
    if (nNodes > MAXN) nNodes = MAXN;
    const int E2 = out_size;   // 2E
    const int Eh = eElems;     // E
    const int nT = (nNodes + 127) / 128;

    const int smem = 2 * 128 * SSTR * (int)sizeof(__half);   // 69632 B
    cudaFuncSetAttribute(gemm_kernel,
                         cudaFuncAttributeMaxDynamicSharedMemorySize, smem);

    wprep_kernel<<<128, 256>>>(W1);
    gemm_kernel<<<2 * nT, 256, smem>>>(zsrc, zdst, b1, nNodes, nT);
    edge_kernel<<<8192, 256>>>(ps, pd, ns, nd, W2, b2,
                               (float*)d_out, E2, Eh, nNodes);
}